// round 1
// baseline (speedup 1.0000x reference)
#include <cuda_runtime.h>
#include <cuda_bf16.h>

#define NN 50000
#define NE 800000
#define IND 128
#define OUTD 64
#define HEADS 4
#define HD 256      // HEADS*OUTD
#define HID 256
#define MOUT 128

// ---- scratch (device globals: allocation-free) ----
__device__ float g_h[(size_t)NN * HD];        // per-head transformed features [N, H*D]
__device__ float g_num[(size_t)NN * HD];      // softmax numerator accum
__device__ float g_hidden[(size_t)NN * HID];  // MLP hidden
__device__ float g_s_src[NN * HEADS];
__device__ float g_s_dst[NN * HEADS];
__device__ float g_den[NN * HEADS];
__device__ float g_Wc[IND * HD];              // repacked W_n -> [IND, H*D]

// ---- pack W_n [H, IND, OUTD] -> Wc [IND, H*OUTD] ----
__global__ void pack_w_kernel(const float* __restrict__ Wn) {
    int i = blockIdx.x * blockDim.x + threadIdx.x;
    if (i < IND * HD) {
        int c = i / HD;
        int j = i % HD;
        int h = j >> 6;
        int d = j & 63;
        g_Wc[i] = Wn[h * (IND * OUTD) + c * OUTD + d];
    }
}

// ---- zero num + den ----
__global__ void zero_kernel() {
    int i = blockIdx.x * blockDim.x + threadIdx.x;
    if (i < NN * HD) g_num[i] = 0.0f;
    if (i < NN * HEADS) g_den[i] = 0.0f;
}

// ---- tiled SIMT GEMM: C[M,N] = act(A' @ B + bias) ----
// AMODE 0: A plain. AMODE 1: A = relu(num/safe_den) computed on load (den per (row,head)).
// EPI   0: none. 1: +bias, relu. 2: +bias.
template<int AMODE, int EPI>
__global__ void gemm_kernel(const float* __restrict__ A, const float* __restrict__ B,
                            const float* __restrict__ bias, const float* __restrict__ den,
                            float* __restrict__ C, int M, int N, int K)
{
    const int BM = 64, BN = 64, BK = 16;
    __shared__ float As[BK][BM + 4];   // row stride 68 floats = 272B (16B aligned)
    __shared__ float Bs[BK][BN];

    int tid = threadIdx.x;            // 256 threads
    int m0 = blockIdx.x * BM;
    int n0 = blockIdx.y * BN;
    int trow = tid >> 4;              // 0..15
    int tcol = tid & 15;              // 0..15

    int arow = tid >> 2;              // 0..63
    int acol = (tid & 3) * 4;         // 0,4,8,12
    int brow = tid >> 4;              // 0..15
    int bcol = (tid & 15) * 4;        // 0..60

    float acc[4][4];
#pragma unroll
    for (int i = 0; i < 4; i++)
#pragma unroll
        for (int j = 0; j < 4; j++) acc[i][j] = 0.0f;

    for (int k0 = 0; k0 < K; k0 += BK) {
        // --- load A tile (64x16) ---
        float4 av = make_float4(0.f, 0.f, 0.f, 0.f);
        int gm = m0 + arow;
        if (gm < M) {
            av = *(const float4*)(A + (size_t)gm * K + k0 + acol);
            if (AMODE == 1) {
                float dv = den[gm * HEADS + ((k0 + acol) >> 6)];
                float inv = dv > 0.0f ? 1.0f / dv : 0.0f;
                av.x = fmaxf(av.x * inv, 0.0f);
                av.y = fmaxf(av.y * inv, 0.0f);
                av.z = fmaxf(av.z * inv, 0.0f);
                av.w = fmaxf(av.w * inv, 0.0f);
            }
        }
        As[acol + 0][arow] = av.x;
        As[acol + 1][arow] = av.y;
        As[acol + 2][arow] = av.z;
        As[acol + 3][arow] = av.w;

        // --- load B tile (16x64): K,N always multiples of tile here ---
        float4 bv = *(const float4*)(B + (size_t)(k0 + brow) * N + n0 + bcol);
        *(float4*)&Bs[brow][bcol] = bv;

        __syncthreads();

#pragma unroll
        for (int k = 0; k < BK; k++) {
            float4 a4 = *(const float4*)&As[k][trow * 4];
            float4 b4 = *(const float4*)&Bs[k][tcol * 4];
            float ar[4] = {a4.x, a4.y, a4.z, a4.w};
            float br[4] = {b4.x, b4.y, b4.z, b4.w};
#pragma unroll
            for (int i = 0; i < 4; i++)
#pragma unroll
                for (int j = 0; j < 4; j++)
                    acc[i][j] = fmaf(ar[i], br[j], acc[i][j]);
        }
        __syncthreads();
    }

#pragma unroll
    for (int i = 0; i < 4; i++) {
        int gm = m0 + trow * 4 + i;
        if (gm >= M) continue;
#pragma unroll
        for (int j = 0; j < 4; j++) {
            int gn = n0 + tcol * 4 + j;
            float v = acc[i][j];
            if (EPI >= 1) v += bias[gn];
            if (EPI == 1) v = fmaxf(v, 0.0f);
            C[(size_t)gm * N + gn] = v;
        }
    }
}

// ---- per-node attention scores: s = <h[n,h,:], a[h,:]> (one warp per node) ----
__global__ void score_kernel(const float* __restrict__ a_src, const float* __restrict__ a_dst) {
    int gw = (blockIdx.x * blockDim.x + threadIdx.x) >> 5;
    int lane = threadIdx.x & 31;
    if (gw >= NN) return;

    const float4* hp = (const float4*)(g_h + (size_t)gw * HD);
    float4 v0 = hp[lane * 2];
    float4 v1 = hp[lane * 2 + 1];

    int head = lane >> 3;           // 8 lanes cover one head (64 dims)
    int off = (lane & 7) * 8;
    const float* as = a_src + head * OUTD + off;
    const float* ad = a_dst + head * OUTD + off;

    float ss = v0.x * as[0] + v0.y * as[1] + v0.z * as[2] + v0.w * as[3]
             + v1.x * as[4] + v1.y * as[5] + v1.z * as[6] + v1.w * as[7];
    float sd = v0.x * ad[0] + v0.y * ad[1] + v0.z * ad[2] + v0.w * ad[3]
             + v1.x * ad[4] + v1.y * ad[5] + v1.z * ad[6] + v1.w * ad[7];

#pragma unroll
    for (int o = 4; o > 0; o >>= 1) {
        ss += __shfl_down_sync(0xffffffffu, ss, o);
        sd += __shfl_down_sync(0xffffffffu, sd, o);
    }
    if ((lane & 7) == 0) {
        g_s_src[gw * HEADS + head] = ss;
        g_s_dst[gw * HEADS + head] = sd;
    }
}

__device__ __forceinline__ void red_add_v4(float* p, float x, float y, float z, float w) {
    asm volatile("red.global.add.v4.f32 [%0], {%1, %2, %3, %4};"
                 :: "l"(p), "f"(x), "f"(y), "f"(z), "f"(w) : "memory");
}

// ---- edge kernel: one warp per edge ----
// ex = exp(leaky_relu(s_src[src]+s_dst[dst]))  (segment-max omitted: shift-invariant, fp32-safe)
// den[dst,h] += ex ; num[dst,h,:] += ex * h[src,h,:]
__global__ void edge_kernel(const int* __restrict__ src, const int* __restrict__ dst) {
    int gw = (blockIdx.x * blockDim.x + threadIdx.x) >> 5;
    int lane = threadIdx.x & 31;
    if (gw >= NE) return;

    int s = src[gw];
    int d = dst[gw];

    float ex = 0.0f;
    if (lane < HEADS) {
        float e = g_s_src[s * HEADS + lane] + g_s_dst[d * HEADS + lane];
        e = e > 0.0f ? e : 0.2f * e;
        ex = __expf(e);
        atomicAdd(&g_den[d * HEADS + lane], ex);
    }
    float exh = __shfl_sync(0xffffffffu, ex, lane >> 3);  // head = lane/8

    const float4* hp = (const float4*)(g_h + (size_t)s * HD);
    float4 v0 = hp[lane * 2];
    float4 v1 = hp[lane * 2 + 1];

    float* np = g_num + (size_t)d * HD + lane * 8;
    red_add_v4(np + 0, exh * v0.x, exh * v0.y, exh * v0.z, exh * v0.w);
    red_add_v4(np + 4, exh * v1.x, exh * v1.y, exh * v1.z, exh * v1.w);
}

extern "C" void kernel_launch(void* const* d_in, const int* in_sizes, int n_in,
                              void* d_out, int out_size) {
    const float* node_emb = (const float*)d_in[0];
    const int*   src      = (const int*)d_in[1];
    const int*   dst      = (const int*)d_in[2];
    const float* W_n      = (const float*)d_in[3];
    const float* a_src    = (const float*)d_in[4];
    const float* a_dst    = (const float*)d_in[5];
    const float* W1       = (const float*)d_in[6];
    const float* b1       = (const float*)d_in[7];
    const float* W2       = (const float*)d_in[8];
    const float* b2       = (const float*)d_in[9];
    float* out = (float*)d_out;

    float* h_ptr;      cudaGetSymbolAddress((void**)&h_ptr, g_h);
    float* num_ptr;    cudaGetSymbolAddress((void**)&num_ptr, g_num);
    float* hid_ptr;    cudaGetSymbolAddress((void**)&hid_ptr, g_hidden);
    float* den_ptr;    cudaGetSymbolAddress((void**)&den_ptr, g_den);
    float* wc_ptr;     cudaGetSymbolAddress((void**)&wc_ptr, g_Wc);

    // 1. repack W, zero accumulators
    pack_w_kernel<<<(IND * HD + 255) / 256, 256>>>(W_n);
    zero_kernel<<<(NN * HD + 255) / 256, 256>>>();

    // 2. GEMM1: h = X @ Wc   [50000,128]x[128,256]
    {
        dim3 grid((NN + 63) / 64, HD / 64);
        gemm_kernel<0, 0><<<grid, 256>>>(node_emb, wc_ptr, nullptr, nullptr,
                                         h_ptr, NN, HD, IND);
    }

    // 3. attention scores per node
    score_kernel<<<(NN * 32 + 255) / 256, 256>>>(a_src, a_dst);

    // 4. edge scatter (softmax numerator/denominator)
    edge_kernel<<<(NE * 32 + 255) / 256, 256>>>(src, dst);

    // 5. GEMM2: hidden = relu( relu(num/den) @ W1 + b1 )   [50000,256]x[256,256]
    {
        dim3 grid((NN + 63) / 64, HID / 64);
        gemm_kernel<1, 1><<<grid, 256>>>(num_ptr, W1, b1, den_ptr,
                                         hid_ptr, NN, HID, HD);
    }

    // 6. GEMM3: out = hidden @ W2 + b2   [50000,256]x[256,128]
    {
        dim3 grid((NN + 63) / 64, MOUT / 64);
        gemm_kernel<0, 2><<<grid, 256>>>(hid_ptr, W2, b2, nullptr,
                                         out, NN, MOUT, HID);
    }
}

// round 2
// speedup vs baseline: 1.4761x; 1.4761x over previous
#include <cuda_runtime.h>
#include <cuda_bf16.h>

#define NN 50000
#define NE 800000
#define IND 128
#define OUTD 64
#define HEADS 4
#define HD 256      // HEADS*OUTD
#define HID 256
#define MOUT 128

// ---- scratch (device globals: allocation-free) ----
__device__ float g_h[(size_t)NN * HD];        // per-head transformed features [N, H*D]
__device__ float g_num[(size_t)NN * HD];      // softmax numerator accum
__device__ float g_hidden[(size_t)NN * HID];  // MLP hidden
__device__ float g_s_src[NN * HEADS];
__device__ float g_s_dst[NN * HEADS];
__device__ float g_den[NN * HEADS];
__device__ float g_Wc[IND * HD];              // repacked W_n -> [IND, H*D]

// ---- pack W_n [H, IND, OUTD] -> Wc [IND, H*OUTD] ----
__global__ void pack_w_kernel(const float* __restrict__ Wn) {
    int i = blockIdx.x * blockDim.x + threadIdx.x;
    if (i < IND * HD) {
        int c = i / HD;
        int j = i % HD;
        int h = j >> 6;
        int d = j & 63;
        g_Wc[i] = Wn[h * (IND * OUTD) + c * OUTD + d];
    }
}

// ---- zero num + den ----
__global__ void zero_kernel() {
    int i = blockIdx.x * blockDim.x + threadIdx.x;
    if (i < NN * HD) g_num[i] = 0.0f;
    if (i < NN * HEADS) g_den[i] = 0.0f;
}

__device__ __forceinline__ unsigned f2tf32(float f) {
    unsigned r;
    asm("cvt.rna.tf32.f32 %0, %1;" : "=r"(r) : "f"(f));
    return r;
}

__device__ __forceinline__ void mma_tf32(float& c0, float& c1, float& c2, float& c3,
                                         unsigned a0, unsigned a1, unsigned a2, unsigned a3,
                                         unsigned b0, unsigned b1) {
    asm volatile("mma.sync.aligned.m16n8k8.row.col.f32.tf32.tf32.f32 "
                 "{%0,%1,%2,%3}, {%4,%5,%6,%7}, {%8,%9}, {%0,%1,%2,%3};"
                 : "+f"(c0), "+f"(c1), "+f"(c2), "+f"(c3)
                 : "r"(a0), "r"(a1), "r"(a2), "r"(a3), "r"(b0), "r"(b1));
}

// ---- tf32 tensor-core GEMM: C[M,N] = act(A' @ B + bias) ----
// BM=128, BN=128, BK=32, 256 threads (8 warps, 4x2 warp grid, each warp 32x64).
// AMODE 0: A plain. AMODE 1: A = relu(num/safe_den) on load (den per (row,head)).
// EPI   0: none. 1: +bias, relu. 2: +bias.
template<int AMODE, int EPI>
__global__ void __launch_bounds__(256)
gemm_tf32_kernel(const float* __restrict__ A, const float* __restrict__ B,
                 const float* __restrict__ bias, const float* __restrict__ den,
                 float* __restrict__ C, int M, int N, int K)
{
    const int BM = 128, BN = 128, BK = 32;
    const int APAD = 36;   // stride so A-frag LDS (4k' + m) is conflict-free
    const int BPAD = 136;  // stride so B-frag LDS (8k' + n) is conflict-free
    __shared__ unsigned As[BM * APAD];   // [m][k]
    __shared__ unsigned Bs[BK * BPAD];   // [k][n]

    int tid = threadIdx.x;
    int wid = tid >> 5;
    int lane = tid & 31;
    int grp = lane >> 2;        // 0..7
    int tig = lane & 3;         // 0..3

    int warp_m = (wid & 3) * 32;   // 4 warps along M
    int warp_n = (wid >> 2) * 64;  // 2 warps along N

    int m0 = blockIdx.x * BM;
    int n0 = blockIdx.y * BN;

    float acc[2][8][4];
#pragma unroll
    for (int i = 0; i < 2; i++)
#pragma unroll
        for (int j = 0; j < 8; j++)
#pragma unroll
            for (int q = 0; q < 4; q++) acc[i][j][q] = 0.0f;

    for (int k0 = 0; k0 < K; k0 += BK) {
        // --- load A tile 128x32 (1024 float4, 4 per thread) ---
#pragma unroll
        for (int j = 0; j < 4; j++) {
            int i = tid + j * 256;
            int row = i >> 3;           // /8 float4 per row
            int c4 = (i & 7) * 4;
            int gm = m0 + row;
            float4 v = make_float4(0.f, 0.f, 0.f, 0.f);
            if (gm < M) {
                v = *(const float4*)(A + (size_t)gm * K + k0 + c4);
                if (AMODE == 1) {
                    float dv = den[gm * HEADS + ((k0 + c4) >> 6)];
                    float inv = dv > 0.0f ? 1.0f / dv : 0.0f;
                    v.x = fmaxf(v.x * inv, 0.0f);
                    v.y = fmaxf(v.y * inv, 0.0f);
                    v.z = fmaxf(v.z * inv, 0.0f);
                    v.w = fmaxf(v.w * inv, 0.0f);
                }
            }
            unsigned* p = &As[row * APAD + c4];
            p[0] = f2tf32(v.x); p[1] = f2tf32(v.y);
            p[2] = f2tf32(v.z); p[3] = f2tf32(v.w);
        }
        // --- load B tile 32x128 (1024 float4, 4 per thread) ---
#pragma unroll
        for (int j = 0; j < 4; j++) {
            int i = tid + j * 256;
            int row = i >> 5;           // /32 float4 per row
            int c4 = (i & 31) * 4;
            float4 v = *(const float4*)(B + (size_t)(k0 + row) * N + n0 + c4);
            unsigned* p = &Bs[row * BPAD + c4];
            p[0] = f2tf32(v.x); p[1] = f2tf32(v.y);
            p[2] = f2tf32(v.z); p[3] = f2tf32(v.w);
        }
        __syncthreads();

#pragma unroll
        for (int kk = 0; kk < BK; kk += 8) {
            unsigned af[2][4];
#pragma unroll
            for (int mt = 0; mt < 2; mt++) {
                int r0 = warp_m + mt * 16 + grp;
                af[mt][0] = As[(r0)     * APAD + kk + tig];
                af[mt][1] = As[(r0 + 8) * APAD + kk + tig];
                af[mt][2] = As[(r0)     * APAD + kk + tig + 4];
                af[mt][3] = As[(r0 + 8) * APAD + kk + tig + 4];
            }
#pragma unroll
            for (int nt = 0; nt < 8; nt++) {
                int nb = warp_n + nt * 8 + grp;
                unsigned b0 = Bs[(kk + tig)     * BPAD + nb];
                unsigned b1 = Bs[(kk + tig + 4) * BPAD + nb];
#pragma unroll
                for (int mt = 0; mt < 2; mt++)
                    mma_tf32(acc[mt][nt][0], acc[mt][nt][1], acc[mt][nt][2], acc[mt][nt][3],
                             af[mt][0], af[mt][1], af[mt][2], af[mt][3], b0, b1);
            }
        }
        __syncthreads();
    }

    // --- epilogue ---
#pragma unroll
    for (int mt = 0; mt < 2; mt++) {
#pragma unroll
        for (int half = 0; half < 2; half++) {
            int gm = m0 + warp_m + mt * 16 + grp + half * 8;
            if (gm >= M) continue;
#pragma unroll
            for (int nt = 0; nt < 8; nt++) {
                int gn = n0 + warp_n + nt * 8 + tig * 2;
                float v0 = acc[mt][nt][half * 2 + 0];
                float v1 = acc[mt][nt][half * 2 + 1];
                if (EPI >= 1) { v0 += bias[gn]; v1 += bias[gn + 1]; }
                if (EPI == 1) { v0 = fmaxf(v0, 0.0f); v1 = fmaxf(v1, 0.0f); }
                *(float2*)(C + (size_t)gm * N + gn) = make_float2(v0, v1);
            }
        }
    }
}

// ---- per-node attention scores: s = <h[n,h,:], a[h,:]> (one warp per node) ----
__global__ void score_kernel(const float* __restrict__ a_src, const float* __restrict__ a_dst) {
    int gw = (blockIdx.x * blockDim.x + threadIdx.x) >> 5;
    int lane = threadIdx.x & 31;
    if (gw >= NN) return;

    const float4* hp = (const float4*)(g_h + (size_t)gw * HD);
    float4 v0 = hp[lane * 2];
    float4 v1 = hp[lane * 2 + 1];

    int head = lane >> 3;           // 8 lanes cover one head (64 dims)
    int off = (lane & 7) * 8;
    const float4* as = (const float4*)(a_src + head * OUTD + off);
    const float4* ad = (const float4*)(a_dst + head * OUTD + off);
    float4 as0 = as[0], as1 = as[1];
    float4 ad0 = ad[0], ad1 = ad[1];

    float ss = v0.x * as0.x + v0.y * as0.y + v0.z * as0.z + v0.w * as0.w
             + v1.x * as1.x + v1.y * as1.y + v1.z * as1.z + v1.w * as1.w;
    float sd = v0.x * ad0.x + v0.y * ad0.y + v0.z * ad0.z + v0.w * ad0.w
             + v1.x * ad1.x + v1.y * ad1.y + v1.z * ad1.z + v1.w * ad1.w;

#pragma unroll
    for (int o = 4; o > 0; o >>= 1) {
        ss += __shfl_down_sync(0xffffffffu, ss, o);
        sd += __shfl_down_sync(0xffffffffu, sd, o);
    }
    if ((lane & 7) == 0) {
        g_s_src[gw * HEADS + head] = ss;
        g_s_dst[gw * HEADS + head] = sd;
    }
}

__device__ __forceinline__ void red_add_v4(float* p, float x, float y, float z, float w) {
    asm volatile("red.global.add.v4.f32 [%0], {%1, %2, %3, %4};"
                 :: "l"(p), "f"(x), "f"(y), "f"(z), "f"(w) : "memory");
}

// ---- edge kernel: one warp per edge ----
// ex = exp(leaky_relu(s_src[src]+s_dst[dst]))  (segment-max omitted: shift-invariant, fp32-safe)
// den[dst,h] += ex ; num[dst,h,:] += ex * h[src,h,:]
__global__ void edge_kernel(const int* __restrict__ src, const int* __restrict__ dst) {
    int gw = (blockIdx.x * blockDim.x + threadIdx.x) >> 5;
    int lane = threadIdx.x & 31;
    if (gw >= NE) return;

    int s = src[gw];
    int d = dst[gw];

    float ex = 0.0f;
    if (lane < HEADS) {
        float e = g_s_src[s * HEADS + lane] + g_s_dst[d * HEADS + lane];
        e = e > 0.0f ? e : 0.2f * e;
        ex = __expf(e);
        atomicAdd(&g_den[d * HEADS + lane], ex);
    }
    float exh = __shfl_sync(0xffffffffu, ex, lane >> 3);  // head = lane/8

    const float4* hp = (const float4*)(g_h + (size_t)s * HD);
    float4 v0 = hp[lane * 2];
    float4 v1 = hp[lane * 2 + 1];

    float* np = g_num + (size_t)d * HD + lane * 8;
    red_add_v4(np + 0, exh * v0.x, exh * v0.y, exh * v0.z, exh * v0.w);
    red_add_v4(np + 4, exh * v1.x, exh * v1.y, exh * v1.z, exh * v1.w);
}

extern "C" void kernel_launch(void* const* d_in, const int* in_sizes, int n_in,
                              void* d_out, int out_size) {
    const float* node_emb = (const float*)d_in[0];
    const int*   src      = (const int*)d_in[1];
    const int*   dst      = (const int*)d_in[2];
    const float* W_n      = (const float*)d_in[3];
    const float* a_src    = (const float*)d_in[4];
    const float* a_dst    = (const float*)d_in[5];
    const float* W1       = (const float*)d_in[6];
    const float* b1       = (const float*)d_in[7];
    const float* W2       = (const float*)d_in[8];
    const float* b2       = (const float*)d_in[9];
    float* out = (float*)d_out;

    float* h_ptr;      cudaGetSymbolAddress((void**)&h_ptr, g_h);
    float* num_ptr;    cudaGetSymbolAddress((void**)&num_ptr, g_num);
    float* hid_ptr;    cudaGetSymbolAddress((void**)&hid_ptr, g_hidden);
    float* den_ptr;    cudaGetSymbolAddress((void**)&den_ptr, g_den);
    float* wc_ptr;     cudaGetSymbolAddress((void**)&wc_ptr, g_Wc);

    // 1. repack W, zero accumulators
    pack_w_kernel<<<(IND * HD + 255) / 256, 256>>>(W_n);
    zero_kernel<<<(NN * HD + 255) / 256, 256>>>();

    // 2. GEMM1: h = X @ Wc   [50000,128]x[128,256]
    {
        dim3 grid((NN + 127) / 128, HD / 128);
        gemm_tf32_kernel<0, 0><<<grid, 256>>>(node_emb, wc_ptr, nullptr, nullptr,
                                              h_ptr, NN, HD, IND);
    }

    // 3. attention scores per node
    score_kernel<<<(NN * 32 + 255) / 256, 256>>>(a_src, a_dst);

    // 4. edge scatter (softmax numerator/denominator)
    edge_kernel<<<(NE * 32 + 255) / 256, 256>>>(src, dst);

    // 5. GEMM2: hidden = relu( relu(num/den) @ W1 + b1 )   [50000,256]x[256,256]
    {
        dim3 grid((NN + 127) / 128, HID / 128);
        gemm_tf32_kernel<1, 1><<<grid, 256>>>(num_ptr, W1, b1, den_ptr,
                                              hid_ptr, NN, HID, HD);
    }

    // 6. GEMM3: out = hidden @ W2 + b2   [50000,256]x[256,128]
    {
        dim3 grid((NN + 127) / 128, MOUT / 128);
        gemm_tf32_kernel<0, 2><<<grid, 256>>>(hid_ptr, W2, b2, nullptr,
                                              out, NN, MOUT, HID);
    }
}